// round 2
// baseline (speedup 1.0000x reference)
#include <cuda_runtime.h>
#include <stdint.h>

#define N_NODES 50000
#define N_EDGES 800000
#define IN_C    128
#define HID_C   128
#define OUT_C   64

// ---------------- scratch (static device globals; no allocation) ------------
__device__ int   g_cnt   [N_NODES];
__device__ int   g_rowptr[N_NODES + 1];
__device__ int   g_cursor[N_NODES];
__device__ int   g_csr   [N_EDGES];
__device__ float g_dinv  [N_NODES];
__device__ float g_h1    [N_NODES * HID_C];   // pre-scaled GEMM1 output
__device__ float g_x2    [N_NODES * HID_C];   // relu(layer-1 out) = layer-2 input
__device__ float g_h2    [N_NODES * OUT_C];   // pre-scaled GEMM2 output

// ---------------- CSR build ---------------------------------------------------
__global__ void k_zero_cnt() {
    int i = blockIdx.x * blockDim.x + threadIdx.x;
    if (i < N_NODES) g_cnt[i] = 0;
}

__global__ void k_count(const int* __restrict__ dst) {
    int e = blockIdx.x * blockDim.x + threadIdx.x;
    if (e < N_EDGES) atomicAdd(&g_cnt[dst[e]], 1);
}

// single-block exclusive scan over 50k counts; also produces dinv
__global__ __launch_bounds__(1024)
void k_scan() {
    __shared__ int ssum[1024];
    const int t  = threadIdx.x;
    const int CH = (N_NODES + 1023) / 1024;          // 49
    int beg = t * CH;
    int end = beg + CH; if (end > N_NODES) end = N_NODES;
    if (beg > N_NODES) beg = N_NODES;

    int s = 0;
    for (int i = beg; i < end; i++) s += g_cnt[i];
    ssum[t] = s;
    __syncthreads();
    // Hillis-Steele inclusive scan
    for (int off = 1; off < 1024; off <<= 1) {
        int v = (t >= off) ? ssum[t - off] : 0;
        __syncthreads();
        ssum[t] += v;
        __syncthreads();
    }
    int run = (t == 0) ? 0 : ssum[t - 1];
    for (int i = beg; i < end; i++) {
        int c = g_cnt[i];
        g_rowptr[i] = run;
        g_cursor[i] = run;
        g_dinv[i]   = rsqrtf(1.0f + (float)c);       // +1 self loop
        run += c;
    }
    if (t == 1023) g_rowptr[N_NODES] = run;
}

__global__ void k_place(const int* __restrict__ src, const int* __restrict__ dst) {
    int e = blockIdx.x * blockDim.x + threadIdx.x;
    if (e >= N_EDGES) return;
    int d = dst[e];
    int idx = atomicAdd(&g_cursor[d], 1);
    g_csr[idx] = src[e];
}

// ---------------- GEMM: H = (X @ W) * dinv[row] -------------------------------
// 128 x COUT block tile, 256 threads, 8 x (COUT/16) per thread.
template <int COUT>
__global__ __launch_bounds__(256)
void k_gemm(const float* __restrict__ X, const float* __restrict__ W,
            float* __restrict__ H)
{
    constexpr int BM = 128;
    constexpr int BK = 16;
    constexpr int TN = COUT / 16;                    // 8 (layer1) / 4 (layer2)

    __shared__ float sX[BK][BM + 4];                 // transposed X tile
    __shared__ float sW[BK][COUT];

    const int tid = threadIdx.x;
    const int tx  = tid & 15;                        // 0..15 -> column group
    const int ty  = tid >> 4;                        // 0..15 -> row group
    const int row0 = blockIdx.x * BM;

    float acc[8][TN];
#pragma unroll
    for (int i = 0; i < 8; i++)
#pragma unroll
        for (int j = 0; j < TN; j++) acc[i][j] = 0.f;

    for (int k0 = 0; k0 < IN_C; k0 += BK) {
        // X tile: 128 rows x 16 cols = 512 float4, 2 per thread; store transposed
#pragma unroll
        for (int i = tid; i < BM * BK / 4; i += 256) {
            int r = i >> 2, q = i & 3;
            int gr = row0 + r;
            float4 v = make_float4(0.f, 0.f, 0.f, 0.f);
            if (gr < N_NODES)
                v = *reinterpret_cast<const float4*>(X + (size_t)gr * IN_C + k0 + 4 * q);
            sX[4 * q + 0][r] = v.x;
            sX[4 * q + 1][r] = v.y;
            sX[4 * q + 2][r] = v.z;
            sX[4 * q + 3][r] = v.w;
        }
        // W tile: rows k0..k0+15 are contiguous
        {
            const float4* wsrc = reinterpret_cast<const float4*>(W + (size_t)k0 * COUT);
            float4* wdst = reinterpret_cast<float4*>(&sW[0][0]);
#pragma unroll
            for (int i = tid; i < BK * COUT / 4; i += 256) wdst[i] = wsrc[i];
        }
        __syncthreads();

#pragma unroll
        for (int k = 0; k < BK; k++) {
            float4 a0 = *reinterpret_cast<const float4*>(&sX[k][ty * 8]);
            float4 a1 = *reinterpret_cast<const float4*>(&sX[k][ty * 8 + 4]);
            float a[8] = {a0.x, a0.y, a0.z, a0.w, a1.x, a1.y, a1.z, a1.w};
            float w[TN];
            {
                float4 w0 = *reinterpret_cast<const float4*>(&sW[k][tx * TN]);
                w[0] = w0.x; w[1] = w0.y; w[2] = w0.z; w[3] = w0.w;
                if (TN == 8) {
                    float4 w1 = *reinterpret_cast<const float4*>(&sW[k][tx * TN + 4]);
                    w[4] = w1.x; w[5] = w1.y; w[6] = w1.z; w[7] = w1.w;
                }
            }
#pragma unroll
            for (int i = 0; i < 8; i++)
#pragma unroll
                for (int j = 0; j < TN; j++)
                    acc[i][j] = fmaf(a[i], w[j], acc[i][j]);
        }
        __syncthreads();
    }

#pragma unroll
    for (int i = 0; i < 8; i++) {
        int gr = row0 + ty * 8 + i;
        if (gr < N_NODES) {
            float dv = g_dinv[gr];
#pragma unroll
            for (int jj = 0; jj < TN / 4; jj++) {
                float4 o = make_float4(acc[i][4 * jj + 0] * dv, acc[i][4 * jj + 1] * dv,
                                       acc[i][4 * jj + 2] * dv, acc[i][4 * jj + 3] * dv);
                *reinterpret_cast<float4*>(H + (size_t)gr * COUT + tx * TN + 4 * jj) = o;
            }
        }
    }
}

// ---------------- layer-1 aggregation: warp per node --------------------------
// x2[n] = relu( dinv[n] * (h1[n] + sum_{s in in(n)} h1[s]) + b1 )
__global__ __launch_bounds__(256)
void k_agg1(const float* __restrict__ b1) {
    int gw   = (blockIdx.x * 256 + threadIdx.x) >> 5;
    int lane = threadIdx.x & 31;
    if (gw >= N_NODES) return;
    const int n = gw;

    const float4* Hq = reinterpret_cast<const float4*>(g_h1);
    float4 acc  = Hq[(size_t)n * 32 + lane];          // self loop (pre-scaled)
    float4 acc2 = make_float4(0.f, 0.f, 0.f, 0.f);

    int e   = g_rowptr[n];
    int end = g_rowptr[n + 1];
    for (; e + 1 < end; e += 2) {
        int s0 = g_csr[e], s1 = g_csr[e + 1];
        float4 v0 = Hq[(size_t)s0 * 32 + lane];
        float4 v1 = Hq[(size_t)s1 * 32 + lane];
        acc.x  += v0.x; acc.y  += v0.y; acc.z  += v0.z; acc.w  += v0.w;
        acc2.x += v1.x; acc2.y += v1.y; acc2.z += v1.z; acc2.w += v1.w;
    }
    if (e < end) {
        int s = g_csr[e];
        float4 v = Hq[(size_t)s * 32 + lane];
        acc.x += v.x; acc.y += v.y; acc.z += v.z; acc.w += v.w;
    }
    acc.x += acc2.x; acc.y += acc2.y; acc.z += acc2.z; acc.w += acc2.w;

    float dv = g_dinv[n];
    float4 b = reinterpret_cast<const float4*>(b1)[lane];
    float4 o;
    o.x = fmaxf(fmaf(acc.x, dv, b.x), 0.f);
    o.y = fmaxf(fmaf(acc.y, dv, b.y), 0.f);
    o.z = fmaxf(fmaf(acc.z, dv, b.z), 0.f);
    o.w = fmaxf(fmaf(acc.w, dv, b.w), 0.f);
    reinterpret_cast<float4*>(g_x2)[(size_t)n * 32 + lane] = o;
}

// ---------------- layer-2 aggregation: half-warp per node ---------------------
// out[n] = dinv[n] * (h2[n] + sum h2[s]) + b2
__global__ __launch_bounds__(256)
void k_agg2(float* __restrict__ out, const float* __restrict__ b2) {
    int gw   = (blockIdx.x * 256 + threadIdx.x) >> 5;
    int lane = threadIdx.x & 31;
    int half = lane >> 4;
    int hl   = lane & 15;
    int n    = gw * 2 + half;
    if (n >= N_NODES) return;

    const float4* Hq = reinterpret_cast<const float4*>(g_h2);
    float4 acc  = Hq[(size_t)n * 16 + hl];            // self loop (pre-scaled)
    float4 acc2 = make_float4(0.f, 0.f, 0.f, 0.f);

    int e   = g_rowptr[n];
    int end = g_rowptr[n + 1];
    for (; e + 1 < end; e += 2) {
        int s0 = g_csr[e], s1 = g_csr[e + 1];
        float4 v0 = Hq[(size_t)s0 * 16 + hl];
        float4 v1 = Hq[(size_t)s1 * 16 + hl];
        acc.x  += v0.x; acc.y  += v0.y; acc.z  += v0.z; acc.w  += v0.w;
        acc2.x += v1.x; acc2.y += v1.y; acc2.z += v1.z; acc2.w += v1.w;
    }
    if (e < end) {
        int s = g_csr[e];
        float4 v = Hq[(size_t)s * 16 + hl];
        acc.x += v.x; acc.y += v.y; acc.z += v.z; acc.w += v.w;
    }
    acc.x += acc2.x; acc.y += acc2.y; acc.z += acc2.z; acc.w += acc2.w;

    float dv = g_dinv[n];
    float4 b = reinterpret_cast<const float4*>(b2)[hl];
    float4 o;
    o.x = fmaf(acc.x, dv, b.x);
    o.y = fmaf(acc.y, dv, b.y);
    o.z = fmaf(acc.z, dv, b.z);
    o.w = fmaf(acc.w, dv, b.w);
    reinterpret_cast<float4*>(out)[(size_t)n * 16 + hl] = o;
}

// ---------------- launch -------------------------------------------------------
extern "C" void kernel_launch(void* const* d_in, const int* in_sizes, int n_in,
                              void* d_out, int out_size)
{
    const float* x  = (const float*)d_in[0];
    const int*   ei = (const int*)  d_in[1];
    const float* W1 = (const float*)d_in[2];
    const float* b1 = (const float*)d_in[3];
    const float* W2 = (const float*)d_in[4];
    const float* b2 = (const float*)d_in[5];
    float* out = (float*)d_out;

    const int* srcp = ei;             // edge_index[0]
    const int* dstp = ei + N_EDGES;   // edge_index[1]

    float *h1, *x2, *h2;
    cudaGetSymbolAddress((void**)&h1, g_h1);
    cudaGetSymbolAddress((void**)&x2, g_x2);
    cudaGetSymbolAddress((void**)&h2, g_h2);

    // CSR build + dinv
    k_zero_cnt<<<(N_NODES + 255) / 256, 256>>>();
    k_count   <<<(N_EDGES + 255) / 256, 256>>>(dstp);
    k_scan    <<<1, 1024>>>();
    k_place   <<<(N_EDGES + 255) / 256, 256>>>(srcp, dstp);

    const int gemm_blocks = (N_NODES + 127) / 128;

    // ---- layer 1 ----
    k_gemm<HID_C><<<gemm_blocks, 256>>>(x, W1, h1);
    k_agg1<<<(N_NODES * 32 + 255) / 256, 256>>>(b1);

    // ---- layer 2 ----
    k_gemm<OUT_C><<<gemm_blocks, 256>>>(x2, W2, h2);
    k_agg2<<<((N_NODES + 1) / 2 * 32 + 255) / 256, 256>>>(out, b2);
}